// round 10
// baseline (speedup 1.0000x reference)
#include <cuda_runtime.h>

#define N_TOK 8192
#define DDIM  256
#define HDIM  64
#define NEXP  32
#define TM    32
#define NCTA  296        // 148 SMs x 2 CTAs: fully resident by construction

typedef unsigned long long u64;

// packed-f32x2 helpers (sm_100+; ptxas never emits FFMA2 from C++)
#define DUP2(d, s)    asm("mov.b64 %0, {%1, %1};" : "=l"(d) : "f"(s))
#define FMA2(c, a, b) asm("fma.rn.f32x2 %0, %1, %2, %0;" : "+l"(c) : "l"(a), "l"(b))
#define UNPK(lo, hi, p) asm("mov.b64 {%0, %1}, %2;" : "=f"(lo), "=f"(hi) : "l"(p))

// ---------------- scratch (no allocations allowed; zero-init, self-resetting) ----------------
__device__ int g_idx[N_TOK];
__device__ int g_counts[NEXP];
__device__ int g_cursor[NEXP];
__device__ int g_perm[N_TOK];
__device__ int g_bar1, g_bar2, g_done;

// grid barrier: all NCTA CTAs are co-resident (2/SM), so spinning is safe.
__device__ __forceinline__ void gsync(int* bar) {
    __syncthreads();
    if (threadIdx.x == 0) {
        __threadfence();                       // release prior writes
        atomicAdd(bar, 1);
        while (*(volatile int*)bar < NCTA) __nanosleep(64);
        __threadfence();                       // acquire
    }
    __syncthreads();
}

__global__ void __launch_bounds__(128) k_moe(const float* __restrict__ x,
                                             const float* __restrict__ rw,
                                             const float* __restrict__ rb,
                                             const float* __restrict__ W1,
                                             const float* __restrict__ b1,
                                             const float* __restrict__ W2,
                                             const float* __restrict__ b2,
                                             float* __restrict__ out) {
    __shared__ __align__(16) char smem_raw[42112];
    __shared__ int s_off[33];

    const int tid = threadIdx.x;
    const int bid = blockIdx.x;

    // ======================= PHASE 1: router GEMM + argmax =======================
    // 256 CTAs x 32 tokens. Thread tile 2 tok x 4 exp in f32x2; K pipelined.
    if (bid < 256) {
        float* Xs   = (float*)smem_raw;                 // [32][36]
        float* Ws   = (float*)(smem_raw + 4608);        // [32][32]
        int*   hist = (int*)(smem_raw + 8704);          // [32]
        const int tx = tid & 7, ty = tid >> 3;
        const int tok0 = bid * 32;

        if (tid < NEXP) hist[tid] = 0;

        const float4* Xg = (const float4*)x;
        const float4* Wg = (const float4*)rw;

        float4 xv[2], wv[2];
#pragma unroll
        for (int i = 0; i < 2; i++) {
            int lin = tid + i * 128;
            xv[i] = Xg[(size_t)(tok0 + (lin & 31)) * 64 + (lin >> 5)];
            wv[i] = Wg[(size_t)(lin & 31) * 64 + (lin >> 5)];
        }

        u64 acc2[4];
#pragma unroll
        for (int j = 0; j < 4; j++) acc2[j] = 0ull;

        for (int c = 0; c < 8; c++) {
#pragma unroll
            for (int i = 0; i < 2; i++) {
                int lin = tid + i * 128;
                int tok = lin & 31, kq = lin >> 5;
                Xs[(kq * 4 + 0) * 36 + tok] = xv[i].x;
                Xs[(kq * 4 + 1) * 36 + tok] = xv[i].y;
                Xs[(kq * 4 + 2) * 36 + tok] = xv[i].z;
                Xs[(kq * 4 + 3) * 36 + tok] = xv[i].w;
                Ws[(kq * 4 + 0) * 32 + tok] = wv[i].x;   // tok == expert idx here
                Ws[(kq * 4 + 1) * 32 + tok] = wv[i].y;
                Ws[(kq * 4 + 2) * 32 + tok] = wv[i].z;
                Ws[(kq * 4 + 3) * 32 + tok] = wv[i].w;
            }
            __syncthreads();
            if (c < 7) {
                int kq0 = (c + 1) * 8;
#pragma unroll
                for (int i = 0; i < 2; i++) {
                    int lin = tid + i * 128;
                    xv[i] = Xg[(size_t)(tok0 + (lin & 31)) * 64 + kq0 + (lin >> 5)];
                    wv[i] = Wg[(size_t)(lin & 31) * 64 + kq0 + (lin >> 5)];
                }
            }
#pragma unroll
            for (int k = 0; k < 32; k++) {
                u64 a = *(const u64*)&Xs[k * 36 + ty * 2];
                float4 bb = *(const float4*)&Ws[k * 32 + tx * 4];
                u64 bd0, bd1, bd2, bd3;
                DUP2(bd0, bb.x); DUP2(bd1, bb.y); DUP2(bd2, bb.z); DUP2(bd3, bb.w);
                FMA2(acc2[0], a, bd0);
                FMA2(acc2[1], a, bd1);
                FMA2(acc2[2], a, bd2);
                FMA2(acc2[3], a, bd3);
            }
            __syncthreads();
        }

        // bias + first-max argmax (strict >, lower-idx ties)
        float4 rbv4 = *(const float4*)&rb[tx * 4];
        float rbv[4] = {rbv4.x, rbv4.y, rbv4.z, rbv4.w};
        float lv[2][4];
#pragma unroll
        for (int j = 0; j < 4; j++) {
            float lo, hi;
            UNPK(lo, hi, acc2[j]);
            lv[0][j] = lo + rbv[j];
            lv[1][j] = hi + rbv[j];
        }
#pragma unroll
        for (int i = 0; i < 2; i++) {
            float v = lv[i][0];
            int idx = tx * 4;
#pragma unroll
            for (int j = 1; j < 4; j++)
                if (lv[i][j] > v) { v = lv[i][j]; idx = tx * 4 + j; }
#pragma unroll
            for (int m = 1; m < 8; m <<= 1) {
                float ov = __shfl_xor_sync(0xffffffffu, v, m);
                int   oi = __shfl_xor_sync(0xffffffffu, idx, m);
                if (ov > v || (ov == v && oi < idx)) { v = ov; idx = oi; }
            }
            if (tx == 0) {
                g_idx[tok0 + ty * 2 + i] = idx;
                atomicAdd(&hist[idx], 1);
            }
        }
        __syncthreads();
        if (tid < NEXP && hist[tid]) atomicAdd(&g_counts[tid], hist[tid]);
    }

    // ======================= grid sync 1 =======================
    gsync(&g_bar1);

    // local 32-wide exclusive scan (every CTA; no extra sync needed)
    if (tid < 32) {
        int c = __ldcg(&g_counts[tid]);
        int s = c;
#pragma unroll
        for (int off = 1; off < 32; off <<= 1) {
            int t = __shfl_up_sync(0xffffffffu, s, off);
            if (tid >= off) s += t;
        }
        s_off[tid] = s - c;
        if (tid == 31) s_off[32] = s;
    }
    __syncthreads();

    // ======================= PHASE 2: scatter (32 CTAs x 256 tokens) =======================
    if (bid < 32) {
        int* hist  = (int*)smem_raw;
        int* sbase = hist + 32;
        int* scur  = hist + 64;
        if (tid < NEXP) { hist[tid] = 0; scur[tid] = 0; }
        __syncthreads();
        int e0 = __ldcg(&g_idx[bid * 256 + tid]);
        int e1 = __ldcg(&g_idx[bid * 256 + 128 + tid]);
        atomicAdd(&hist[e0], 1);
        atomicAdd(&hist[e1], 1);
        __syncthreads();
        if (tid < NEXP && hist[tid])
            sbase[tid] = s_off[tid] + atomicAdd(&g_cursor[tid], hist[tid]);
        __syncthreads();
        int r0 = atomicAdd(&scur[e0], 1);
        g_perm[sbase[e0] + r0] = bid * 256 + tid;
        int r1 = atomicAdd(&scur[e1], 1);
        g_perm[sbase[e1] + r1] = bid * 256 + 128 + tid;
    }

    // ======================= grid sync 2 =======================
    gsync(&g_bar2);

    // safe resets for next graph replay (all CTAs are past phase 1/2 now)
    if (bid == 0) {
        if (tid < NEXP) { g_counts[tid] = 0; g_cursor[tid] = 0; }
        if (tid == 0) g_bar1 = 0;
    }

    // ======================= PHASE 3: grouped expert FFN =======================
    // map bid -> (expert e, tile) using the smem scan
    int e = -1, tile = 0;
    {
        int t = bid, acc = 0, prev = s_off[0];
#pragma unroll
        for (int ee = 0; ee < NEXP; ee++) {
            int nxt = s_off[ee + 1];
            int tiles_e = (nxt - prev + TM - 1) >> 5;
            if (e < 0 && t < acc + tiles_e) { e = ee; tile = t - acc; }
            acc += tiles_e;
            prev = nxt;
        }
    }

    if (e >= 0) {
        const int off0 = s_off[e];
        const int cnt  = s_off[e + 1] - off0;

        const int tx = tid & 15;       // 16 h-groups of 4
        const int ty = tid >> 4;       // 8 token-groups of 4

        int rem = cnt - tile * TM;
        const int nt = rem > TM ? TM : rem;

        int*   toks  = (int*)smem_raw;                  // [32]
        float* Hs    = (float*)(smem_raw + 128);        // [64][36]
        float* arena = (float*)(smem_raw + 9344);       // 8192 floats
#define XS(b,k,t)   arena[(b)*1152 + (k)*36 + (t)]
#define WB1(b,k,h)  arena[2304 + (b)*2048 + (k)*64 + (h)]
#define WB2(b,k,nn) arena[(b)*4096 + (k)*64 + (nn)]

        if (tid < TM) toks[tid] = __ldcg(&g_perm[off0 + min(tile * TM + tid, cnt - 1)]);
        __syncthreads();

        const float4* Xg  = (const float4*)x;
        const float4* Wg1 = (const float4*)(W1 + (size_t)e * DDIM * HDIM);
        const float4* W2g = (const float4*)(W2 + (size_t)e * HDIM * DDIM);

        const int tokA = tid & 31, kqA = tid >> 5;
        const int tokB = tokA,     kqB = kqA + 4;

        float4 xv0, xv1, wv[4];
        xv0 = Xg[(size_t)toks[tokA] * 64 + kqA];
        xv1 = Xg[(size_t)toks[tokB] * 64 + kqB];
#pragma unroll
        for (int i = 0; i < 4; i++) wv[i] = Wg1[tid + i * 128];

        u64 acc2[2][4];
#pragma unroll
        for (int p = 0; p < 2; p++)
#pragma unroll
            for (int j = 0; j < 4; j++) acc2[p][j] = 0ull;

        // GEMM1: 8 chunks of K=32, reg-prefetch pipelined
        for (int c = 0; c < 8; c++) {
            const int b = c & 1;
            XS(b, kqA * 4 + 0, tokA) = xv0.x;
            XS(b, kqA * 4 + 1, tokA) = xv0.y;
            XS(b, kqA * 4 + 2, tokA) = xv0.z;
            XS(b, kqA * 4 + 3, tokA) = xv0.w;
            XS(b, kqB * 4 + 0, tokB) = xv1.x;
            XS(b, kqB * 4 + 1, tokB) = xv1.y;
            XS(b, kqB * 4 + 2, tokB) = xv1.z;
            XS(b, kqB * 4 + 3, tokB) = xv1.w;
#pragma unroll
            for (int i = 0; i < 4; i++) {
                int lin = tid + i * 128;
                *(float4*)&WB1(b, lin >> 4, (lin & 15) * 4) = wv[i];
            }
            if (c < 7) {
                int k0 = (c + 1) * 32;
                xv0 = Xg[(size_t)toks[tokA] * 64 + (k0 >> 2) + kqA];
                xv1 = Xg[(size_t)toks[tokB] * 64 + (k0 >> 2) + kqB];
#pragma unroll
                for (int i = 0; i < 4; i++) wv[i] = Wg1[(k0 << 4) + tid + i * 128];
            }
            __syncthreads();
#pragma unroll
            for (int k = 0; k < 32; k++) {
                ulonglong2 a = *(const ulonglong2*)&XS(b, k, ty * 4);
                float4 bb = *(const float4*)&WB1(b, k, tx * 4);
                u64 bd0, bd1, bd2, bd3;
                DUP2(bd0, bb.x); DUP2(bd1, bb.y); DUP2(bd2, bb.z); DUP2(bd3, bb.w);
                FMA2(acc2[0][0], a.x, bd0); FMA2(acc2[1][0], a.y, bd0);
                FMA2(acc2[0][1], a.x, bd1); FMA2(acc2[1][1], a.y, bd1);
                FMA2(acc2[0][2], a.x, bd2); FMA2(acc2[1][2], a.y, bd2);
                FMA2(acc2[0][3], a.x, bd3); FMA2(acc2[1][3], a.y, bd3);
            }
        }

        // bias + relu -> Hs[h][tok]
        {
            float4 bb = *(const float4*)&b1[e * HDIM + tx * 4];
            float bv[4] = {bb.x, bb.y, bb.z, bb.w};
#pragma unroll
            for (int p = 0; p < 2; p++) {
#pragma unroll
                for (int j = 0; j < 4; j++) {
                    float lo, hi;
                    UNPK(lo, hi, acc2[p][j]);
                    lo += bv[j]; hi += bv[j];
                    Hs[(tx * 4 + j) * 36 + ty * 4 + 2 * p]     = lo > 0.f ? lo : 0.f;
                    Hs[(tx * 4 + j) * 36 + ty * 4 + 2 * p + 1] = hi > 0.f ? hi : 0.f;
                }
            }
        }

        float4 wv2[8];
#pragma unroll
        for (int i = 0; i < 8; i++) {
            int lin = tid + i * 128;
            wv2[i] = W2g[(lin >> 4) * 64 + (lin & 15)];
        }
        __syncthreads();

        // GEMM2: 4 chunks of 64 output cols
        for (int c = 0; c < 4; c++) {
            const int b = c & 1;
#pragma unroll
            for (int i = 0; i < 8; i++) {
                int lin = tid + i * 128;
                *(float4*)&WB2(b, lin >> 4, (lin & 15) * 4) = wv2[i];
            }
            if (c < 3) {
#pragma unroll
                for (int i = 0; i < 8; i++) {
                    int lin = tid + i * 128;
                    wv2[i] = W2g[(lin >> 4) * 64 + (c + 1) * 16 + (lin & 15)];
                }
            }
            __syncthreads();

#pragma unroll
            for (int p = 0; p < 2; p++)
#pragma unroll
                for (int j = 0; j < 4; j++) acc2[p][j] = 0ull;

#pragma unroll 8
            for (int k = 0; k < HDIM; k++) {
                ulonglong2 a = *(const ulonglong2*)&Hs[k * 36 + ty * 4];
                float4 bb = *(const float4*)&WB2(b, k, tx * 4);
                u64 bd0, bd1, bd2, bd3;
                DUP2(bd0, bb.x); DUP2(bd1, bb.y); DUP2(bd2, bb.z); DUP2(bd3, bb.w);
                FMA2(acc2[0][0], a.x, bd0); FMA2(acc2[1][0], a.y, bd0);
                FMA2(acc2[0][1], a.x, bd1); FMA2(acc2[1][1], a.y, bd1);
                FMA2(acc2[0][2], a.x, bd2); FMA2(acc2[1][2], a.y, bd2);
                FMA2(acc2[0][3], a.x, bd3); FMA2(acc2[1][3], a.y, bd3);
            }

            float4 cb = *(const float4*)&b2[e * DDIM + c * 64 + tx * 4];
            float cv[4] = {cb.x, cb.y, cb.z, cb.w};
            float r[4][4];
#pragma unroll
            for (int p = 0; p < 2; p++) {
#pragma unroll
                for (int j = 0; j < 4; j++) {
                    float lo, hi;
                    UNPK(lo, hi, acc2[p][j]);
                    r[2 * p][j]     = fmaxf(lo + cv[j], 0.f);
                    r[2 * p + 1][j] = fmaxf(hi + cv[j], 0.f);
                }
            }
#pragma unroll
            for (int i = 0; i < 4; i++) {
                int ti = ty * 4 + i;
                if (ti < nt) {
                    size_t row = (size_t)toks[ti] * DDIM;
                    float4 rv;
                    rv.x = r[i][0]; rv.y = r[i][1]; rv.z = r[i][2]; rv.w = r[i][3];
                    *(float4*)&out[row + c * 64 + tx * 4] = rv;
                }
            }
        }
#undef XS
#undef WB1
#undef WB2
    }

    // ======================= epilogue: reset bar2/done for next replay =======================
    __syncthreads();
    if (tid == 0) {
        __threadfence();
        int d = atomicAdd(&g_done, 1);
        if (d == NCTA - 1) { g_done = 0; g_bar2 = 0; }
    }
}

// ---------------- launch ----------------
extern "C" void kernel_launch(void* const* d_in, const int* in_sizes, int n_in,
                              void* d_out, int out_size) {
    const float* x   = (const float*)d_in[0];
    const float* rw  = (const float*)d_in[1];
    const float* rb  = (const float*)d_in[2];
    const float* W1  = (const float*)d_in[3];
    const float* b1  = (const float*)d_in[4];
    const float* W2  = (const float*)d_in[5];
    const float* b2  = (const float*)d_in[6];
    float* out = (float*)d_out;

    k_moe<<<NCTA, 128>>>(x, rw, rb, W1, b1, W2, b2, out);
}